// round 2
// baseline (speedup 1.0000x reference)
#include <cuda_runtime.h>
#include <cuda_bf16.h>
#include <math.h>
#include <stdint.h>

// Problem constants
#define TT  512
#define BB  32
#define HH  256      // per-direction hidden
#define EMB_ 256
#define HID_ 512
#define KK  24
#define START_TAG 22
#define STOP_TAG 23
#define NEGV (-10000.0f)

// ---------------------------------------------------------------------------
// Device scratch (allocation-free rule: __device__ globals)
// ---------------------------------------------------------------------------
__device__ float g_ig[2][TT][1024][BB];      // input-gate preactivations, [dir][t][gatecol][b]  (128 MB)
__device__ float g_hall[TT][HID_][BB];       // concat hidden states, [t][hid][b], hid = dir*256+col (32 MB)
__device__ float g_h[2][2][HH][BB];          // h double buffer: [phase][dir][col][b]
__device__ float g_feats[TT][BB][KK];        // CRF emission feats
__device__ unsigned g_bar_count[2];
__device__ volatile unsigned g_bar_gen[2];

// ---------------------------------------------------------------------------
// Per-direction software grid barrier (64 blocks per direction, all resident)
// ---------------------------------------------------------------------------
__device__ __forceinline__ void dir_barrier(int dir) {
    __syncthreads();
    if (threadIdx.x == 0) {
        __threadfence();
        unsigned gen = g_bar_gen[dir];
        if (atomicAdd(&g_bar_count[dir], 1u) == 63u) {
            g_bar_count[dir] = 0u;
            __threadfence();
            g_bar_gen[dir] = gen + 1u;
        } else {
            while (g_bar_gen[dir] == gen) { }
            __threadfence();
        }
    }
    __syncthreads();
}

// ---------------------------------------------------------------------------
// Kernel 1: ig[d][t][col][b] = emb[sent[b][t]] @ W_ih^T + b_ih + b_hh
// grid = 1024 (d*512 + t), block = 256.  smem: x_s[256][34], w_s[64][256]
// ---------------------------------------------------------------------------
__global__ void __launch_bounds__(256) ig_kernel(
    const int* __restrict__ sentence, const float* __restrict__ emb,
    const float* __restrict__ w_ih_f, const float* __restrict__ b_ih_f, const float* __restrict__ b_hh_f,
    const float* __restrict__ w_ih_b, const float* __restrict__ b_ih_b, const float* __restrict__ b_hh_b)
{
    extern __shared__ float sm[];
    float* x_s = sm;                  // [e][b] stride 34 (pad: conflict-free, float2-aligned)
    float* w_s = sm + 256 * 34;       // [c][e] 64x256 chunk

    int d = blockIdx.x >> 9;
    int t = blockIdx.x & 511;
    const float* w_ih = d ? w_ih_b : w_ih_f;
    const float* bi   = d ? b_ih_b : b_ih_f;
    const float* bh   = d ? b_hh_b : b_hh_f;
    int tid = threadIdx.x;

    // gather embedding rows: x_s[e][b], e = tid (coalesced over e per row)
    for (int b = 0; b < BB; ++b) {
        int tok = __ldg(&sentence[b * TT + t]);
        x_s[tid * 34 + b] = __ldg(&emb[tok * EMB_ + tid]);
    }

    int bh2 = tid & 15;               // batch pair index
    int b2  = bh2 * 2;
    int cg  = tid >> 4;               // 16 col-groups of 4 cols

    for (int chunk = 0; chunk < 16; ++chunk) {
        int colBase = chunk * 64;
        __syncthreads();              // prior reads of w_s / x_s writes done
        for (int i = tid; i < 64 * 256; i += 256)
            w_s[i] = w_ih[colBase * 256 + i];          // coalesced
        __syncthreads();

        float a0=0.f,a1=0.f,a2=0.f,a3=0.f,a4=0.f,a5=0.f,a6=0.f,a7=0.f;
        #pragma unroll 4
        for (int e = 0; e < 256; ++e) {
            float2 xv = *(const float2*)&x_s[e * 34 + b2];
            float w0 = w_s[(cg*4+0)*256 + e];
            float w1 = w_s[(cg*4+1)*256 + e];
            float w2 = w_s[(cg*4+2)*256 + e];
            float w3 = w_s[(cg*4+3)*256 + e];
            a0 += xv.x*w0; a1 += xv.y*w0;
            a2 += xv.x*w1; a3 += xv.y*w1;
            a4 += xv.x*w2; a5 += xv.y*w2;
            a6 += xv.x*w3; a7 += xv.y*w3;
        }
        float r[8] = {a0,a1,a2,a3,a4,a5,a6,a7};
        #pragma unroll
        for (int j = 0; j < 4; ++j) {
            int col = colBase + cg * 4 + j;
            float bias = __ldg(&bi[col]) + __ldg(&bh[col]);
            g_ig[d][t][col][b2]   = r[2*j]   + bias;
            g_ig[d][t][col][b2+1] = r[2*j+1] + bias;
        }
    }
}

// ---------------------------------------------------------------------------
// Kernel 2: persistent bidirectional LSTM recurrence.
// grid = 128 (dir = bx>>6, 64 blocks/dir, each owns 4 h-cols = 16 gate cols)
// block = 256.  smem: w_s[16][256], h_s[256][32], g_s[16][32]
// ---------------------------------------------------------------------------
__global__ void __launch_bounds__(256) lstm_rec(
    const float* __restrict__ w_hh_f, const float* __restrict__ w_hh_b,
    const float* __restrict__ h0, const float* __restrict__ c0)
{
    extern __shared__ float sm[];
    float* w_s = sm;                  // [l][k]  l = gate*4 + sub
    float* h_s = sm + 16 * 256;       // [k][b]
    float* g_s = sm + 16 * 256 + 256 * 32;  // [l][b]

    int bx  = blockIdx.x;
    int dir = bx >> 6;
    int blk = bx & 63;
    int j0  = blk * 4;                // first owned h-col
    const float* w_hh = dir ? w_hh_b : w_hh_f;
    int tid = threadIdx.x;
    int b   = tid & 31;

    // stage W_hh rows for our 16 gate columns
    for (int i = tid; i < 16 * 256; i += 256) {
        int l = i >> 8, k = i & 255;
        int gc = (l >> 2) * 256 + j0 + (l & 3);
        w_s[i] = w_hh[gc * 256 + k];
    }

    // init c (register-resident, per activation thread) and h phase 0
    float c_reg = 0.f;
    if (tid < 128) {
        int jl = tid >> 5;
        int col = j0 + jl;
        c_reg = c0[dir * (BB*HH) + b * HH + col];
        g_h[0][dir][col][b] = h0[dir * (BB*HH) + b * HH + col];
    }
    __threadfence();
    dir_barrier(dir);

    int cg = tid >> 5;
    int l0 = cg * 2, l1 = l0 + 1;
    int gc0 = (l0 >> 2) * 256 + j0 + (l0 & 3);
    int gc1 = (l1 >> 2) * 256 + j0 + (l1 & 3);

    for (int t = 0; t < TT; ++t) {
        int tt = dir ? (TT - 1 - t) : t;
        int ph = t & 1;

        // stage full h into smem (coalesced flat copy from L2)
        const float* hg = &g_h[ph][dir][0][0];
        for (int i = tid; i < HH * BB; i += 256) h_s[i] = hg[i];
        __syncthreads();

        float a0 = g_ig[dir][tt][gc0][b];
        float a1 = g_ig[dir][tt][gc1][b];
        #pragma unroll 8
        for (int k = 0; k < 256; k += 4) {
            float4 w0 = *(const float4*)&w_s[l0 * 256 + k];
            float4 w1 = *(const float4*)&w_s[l1 * 256 + k];
            float hv0 = h_s[(k+0)*32 + b];
            float hv1 = h_s[(k+1)*32 + b];
            float hv2 = h_s[(k+2)*32 + b];
            float hv3 = h_s[(k+3)*32 + b];
            a0 += w0.x*hv0; a1 += w1.x*hv0;
            a0 += w0.y*hv1; a1 += w1.y*hv1;
            a0 += w0.z*hv2; a1 += w1.z*hv2;
            a0 += w0.w*hv3; a1 += w1.w*hv3;
        }
        g_s[l0 * 32 + b] = a0;
        g_s[l1 * 32 + b] = a1;
        __syncthreads();

        if (tid < 128) {
            int jl = tid >> 5;
            float gi = g_s[(0  + jl) * 32 + b];
            float gf = g_s[(4  + jl) * 32 + b];
            float gg = g_s[(8  + jl) * 32 + b];
            float go = g_s[(12 + jl) * 32 + b];
            float iv = 1.f / (1.f + expf(-gi));
            float fv = 1.f / (1.f + expf(-gf));
            float gv = tanhf(gg);
            float ov = 1.f / (1.f + expf(-go));
            c_reg = fv * c_reg + iv * gv;
            float hv = ov * tanhf(c_reg);
            int col = j0 + jl;
            g_h[ph ^ 1][dir][col][b] = hv;
            g_hall[tt][dir * HH + col][b] = hv;
        }
        __threadfence();
        dir_barrier(dir);
    }
}

// ---------------------------------------------------------------------------
// Kernel 3: feats[t][b][k] = hs[t][b][:] @ w_out[k][:] + b_out[k]
// grid = 512 (t), block = 768 (b = tid&31, k = tid>>5)
// ---------------------------------------------------------------------------
__global__ void __launch_bounds__(768) feats_kernel(
    const float* __restrict__ w_out, const float* __restrict__ b_out)
{
    extern __shared__ float sm[];
    float* h_sh = sm;                 // [hid][b]
    float* w_sh = sm + HID_ * BB;     // [k][hid]
    int t = blockIdx.x, tid = threadIdx.x;
    const float* hg = &g_hall[t][0][0];
    for (int i = tid; i < HID_ * BB; i += 768) h_sh[i] = hg[i];
    for (int i = tid; i < KK * HID_; i += 768) w_sh[i] = w_out[i];
    __syncthreads();
    int b = tid & 31, k = tid >> 5;
    float acc = 0.f;
    #pragma unroll 8
    for (int j = 0; j < HID_; ++j)
        acc += h_sh[j * 32 + b] * w_sh[k * HID_ + j];
    g_feats[t][b][k] = acc + __ldg(&b_out[k]);
}

// ---------------------------------------------------------------------------
// Kernel 4: Viterbi forward + backtrace. 1 warp per batch; bp in smem.
// Matches jnp.argmax first-max tie-breaking.
// ---------------------------------------------------------------------------
__global__ void __launch_bounds__(32) viterbi_kernel(
    const float* __restrict__ transitions, float* __restrict__ out)
{
    __shared__ unsigned char bp_s[TT][KK];
    int bb = blockIdx.x, lane = threadIdx.x;

    float tr[KK];
    #pragma unroll
    for (int j = 0; j < KK; ++j)
        tr[j] = (lane < KK) ? transitions[lane * KK + j] : 0.f;

    float fvv = (lane == START_TAG) ? 0.f : NEGV;

    for (int t = 0; t < TT; ++t) {
        float best = -3.402823466e38f; int arg = 0;
        #pragma unroll
        for (int p = 0; p < KK; ++p) {
            float s = __shfl_sync(0xffffffffu, fvv, p) + tr[p];
            if (s > best) { best = s; arg = p; }   // strict > keeps first max
        }
        float feat = (lane < KK) ? g_feats[t][bb][lane] : 0.f;
        fvv = best + feat;
        if (lane < KK) bp_s[t][lane] = (unsigned char)arg;
    }

    float term = (lane < KK) ? (fvv + transitions[STOP_TAG * KK + lane])
                             : -3.402823466e38f;
    int idx = lane;
    #pragma unroll
    for (int off = 16; off > 0; off >>= 1) {
        float v2 = __shfl_down_sync(0xffffffffu, term, off);
        int   i2 = __shfl_down_sync(0xffffffffu, idx,  off);
        if (v2 > term || (v2 == term && i2 < idx)) { term = v2; idx = i2; }
    }
    if (lane == 0) {
        out[bb] = term;                       // path score
        int tag = idx;
        for (int t = TT - 1; t >= 0; --t) {
            out[BB + bb * TT + t] = (float)tag;
            tag = bp_s[t][tag];
        }
    }
}

// ---------------------------------------------------------------------------
// Launch
// ---------------------------------------------------------------------------
static const int IG_SMEM  = (256 * 34 + 64 * 256) * 4;                 // 100352
static const int REC_SMEM = (16 * 256 + 256 * 32 + 16 * 32) * 4;      // 51200
static const int FE_SMEM  = (HID_ * BB + KK * HID_) * 4;              // 114688

extern "C" void kernel_launch(void* const* d_in, const int* in_sizes, int n_in,
                              void* d_out, int out_size)
{
    const int*   sentence    = (const int*)  d_in[0];
    const float* embedding   = (const float*)d_in[1];
    const float* w_ih_f      = (const float*)d_in[2];
    const float* w_hh_f      = (const float*)d_in[3];
    const float* b_ih_f      = (const float*)d_in[4];
    const float* b_hh_f      = (const float*)d_in[5];
    const float* w_ih_b      = (const float*)d_in[6];
    const float* w_hh_b      = (const float*)d_in[7];
    const float* b_ih_b      = (const float*)d_in[8];
    const float* b_hh_b      = (const float*)d_in[9];
    const float* w_out       = (const float*)d_in[10];
    const float* b_out       = (const float*)d_in[11];
    const float* transitions = (const float*)d_in[12];
    const float* h0          = (const float*)d_in[13];
    const float* c0          = (const float*)d_in[14];
    float* out = (float*)d_out;

    cudaFuncSetAttribute(ig_kernel,   cudaFuncAttributeMaxDynamicSharedMemorySize, IG_SMEM);
    cudaFuncSetAttribute(lstm_rec,    cudaFuncAttributeMaxDynamicSharedMemorySize, REC_SMEM);
    cudaFuncSetAttribute(feats_kernel,cudaFuncAttributeMaxDynamicSharedMemorySize, FE_SMEM);

    ig_kernel<<<1024, 256, IG_SMEM>>>(sentence, embedding,
                                      w_ih_f, b_ih_f, b_hh_f,
                                      w_ih_b, b_ih_b, b_hh_b);
    lstm_rec<<<128, 256, REC_SMEM>>>(w_hh_f, w_hh_b, h0, c0);
    feats_kernel<<<512, 768, FE_SMEM>>>(w_out, b_out);
    viterbi_kernel<<<32, 32>>>(transitions, out);
}